// round 8
// baseline (speedup 1.0000x reference)
#include <cuda_runtime.h>
#include <cuda_bf16.h>
#include <stdint.h>

// Scatter-mean via counting-sort + gather (no atomics in the hot loop).
// Pipeline: detect id dtype -> init -> histogram(x4) -> 3-stage parallel scan ->
//           build permutation(x4) -> gather (warp-staged indices, 4-wide MLP).
// Fallback to a direct-atomic path for shapes exceeding static scratch.

#define MAX_NODES (1 << 20)
#define PERM_CAP  (1 << 21)
#define SCAN_TILE 4096
#define MAX_SCAN_BLOCKS ((MAX_NODES + SCAN_TILE - 1) / SCAN_TILE)

__device__ int g_is64;
__device__ int g_count[MAX_NODES];
__device__ int g_start[MAX_NODES];
__device__ int g_cursor[MAX_NODES];
__device__ int g_perm[PERM_CAP];
__device__ int g_bsum[MAX_SCAN_BLOCKS];
__device__ int g_boff[MAX_SCAN_BLOCKS];
__device__ float g_fcounts[MAX_NODES];   // fallback path only

// ---------- dtype detect ----------
__global__ void detect_kernel(const unsigned int* __restrict__ words, int M) {
    __shared__ int any_nonzero;
    if (threadIdx.x == 0) any_nonzero = 0;
    __syncthreads();
    int n = (M / 2) < 4096 ? (M / 2) : 4096;
    for (int i = threadIdx.x; i < n; i += blockDim.x)
        if (words[2 * i + 1] != 0u) any_nonzero = 1;   // int64 high word
    __syncthreads();
    if (threadIdx.x == 0) g_is64 = any_nonzero ? 0 : 1;
}

__device__ __forceinline__ int load_id(const void* ids, int i, bool is64) {
    return is64 ? (int)((const long long*)ids)[i] : ((const int*)ids)[i];
}

// ---------- fast path ----------
__global__ void init_kernel(float* __restrict__ ids_out, int N, int has_ids) {
    int i = blockIdx.x * blockDim.x + threadIdx.x;
    int stride = gridDim.x * blockDim.x;
    for (; i < N; i += stride) {
        g_count[i] = 0;
        if (has_ids) ids_out[i] = (float)i;
    }
}

// Histogram: 4 independent RED ops in flight per thread-iteration.
__global__ void hist_kernel(const void* __restrict__ ids, int M) {
    bool is64 = g_is64;
    int t = blockIdx.x * blockDim.x + threadIdx.x;
    int stride = gridDim.x * blockDim.x;
    int M4 = M >> 2;
    if (is64) {
        const longlong2* p = (const longlong2*)ids;
        for (int i = t; i < M4; i += stride) {
            longlong2 a = p[2 * i], b = p[2 * i + 1];
            atomicAdd(&g_count[(int)a.x], 1);
            atomicAdd(&g_count[(int)a.y], 1);
            atomicAdd(&g_count[(int)b.x], 1);
            atomicAdd(&g_count[(int)b.y], 1);
        }
    } else {
        const int4* p = (const int4*)ids;
        for (int i = t; i < M4; i += stride) {
            int4 a = p[i];
            atomicAdd(&g_count[a.x], 1);
            atomicAdd(&g_count[a.y], 1);
            atomicAdd(&g_count[a.z], 1);
            atomicAdd(&g_count[a.w], 1);
        }
    }
    for (int i = M4 * 4 + t; i < M; i += stride)
        atomicAdd(&g_count[load_id(ids, i, is64)], 1);
}

// ----- 3-stage scan: partial sums -> scan of block sums -> final rescan -----
__global__ void scan_partial(int N) {
    __shared__ int wsum[32];
    int b = blockIdx.x, tid = threadIdx.x;
    int lane = tid & 31, warp = tid >> 5;
    int base = b * SCAN_TILE + tid * 4;
    int s = 0;
    #pragma unroll
    for (int k = 0; k < 4; k++) {
        int i = base + k;
        if (i < N) s += g_count[i];
    }
    #pragma unroll
    for (int o = 16; o > 0; o >>= 1) s += __shfl_down_sync(0xffffffffu, s, o);
    if (lane == 0) wsum[warp] = s;
    __syncthreads();
    if (warp == 0) {
        int w = wsum[lane];
        #pragma unroll
        for (int o = 16; o > 0; o >>= 1) w += __shfl_down_sync(0xffffffffu, w, o);
        if (lane == 0) g_bsum[b] = w;
    }
}

__global__ void scan_tops(int nb) {   // 1 block, nb <= 1024
    __shared__ int wsum[32];
    int tid = threadIdx.x, lane = tid & 31, warp = tid >> 5;
    int s = (tid < nb) ? g_bsum[tid] : 0;
    int x = s;
    #pragma unroll
    for (int o = 1; o < 32; o <<= 1) {
        int y = __shfl_up_sync(0xffffffffu, x, o);
        if (lane >= o) x += y;
    }
    if (lane == 31) wsum[warp] = x;
    __syncthreads();
    if (warp == 0) {
        int w = wsum[lane];
        #pragma unroll
        for (int o = 1; o < 32; o <<= 1) {
            int y = __shfl_up_sync(0xffffffffu, w, o);
            if (lane >= o) w += y;
        }
        wsum[lane] = w;
    }
    __syncthreads();
    if (tid < nb) g_boff[tid] = x - s + (warp > 0 ? wsum[warp - 1] : 0);
}

__global__ void scan_final(int N) {
    __shared__ int wsum[32];
    __shared__ int boff;
    int b = blockIdx.x, tid = threadIdx.x;
    int lane = tid & 31, warp = tid >> 5;
    if (tid == 0) boff = g_boff[b];
    int base = b * SCAN_TILE + tid * 4;
    int v[4]; int s = 0;
    #pragma unroll
    for (int k = 0; k < 4; k++) {
        int i = base + k;
        v[k] = (i < N) ? g_count[i] : 0;
        s += v[k];
    }
    int x = s;
    #pragma unroll
    for (int o = 1; o < 32; o <<= 1) {
        int y = __shfl_up_sync(0xffffffffu, x, o);
        if (lane >= o) x += y;
    }
    if (lane == 31) wsum[warp] = x;
    __syncthreads();
    if (warp == 0) {
        int w = wsum[lane];
        #pragma unroll
        for (int o = 1; o < 32; o <<= 1) {
            int y = __shfl_up_sync(0xffffffffu, w, o);
            if (lane >= o) w += y;
        }
        wsum[lane] = w;
    }
    __syncthreads();
    int run = x - s + (warp > 0 ? wsum[warp - 1] : 0) + boff;
    #pragma unroll
    for (int k = 0; k < 4; k++) {
        int i = base + k;
        if (i < N) {
            g_start[i]  = run;
            g_cursor[i] = run;
            run += v[k];
        }
    }
}

// Permutation: 4 independent atomic chains in flight per thread-iteration.
__global__ void build_perm_kernel(const void* __restrict__ ids, int M) {
    bool is64 = g_is64;
    int t = blockIdx.x * blockDim.x + threadIdx.x;
    int stride = gridDim.x * blockDim.x;
    int M4 = M >> 2;
    if (is64) {
        const longlong2* p = (const longlong2*)ids;
        for (int i = t; i < M4; i += stride) {
            longlong2 a = p[2 * i], b = p[2 * i + 1];
            int p0 = atomicAdd(&g_cursor[(int)a.x], 1);
            int p1 = atomicAdd(&g_cursor[(int)a.y], 1);
            int p2 = atomicAdd(&g_cursor[(int)b.x], 1);
            int p3 = atomicAdd(&g_cursor[(int)b.y], 1);
            int base = 4 * i;
            g_perm[p0] = base;
            g_perm[p1] = base + 1;
            g_perm[p2] = base + 2;
            g_perm[p3] = base + 3;
        }
    } else {
        const int4* p = (const int4*)ids;
        for (int i = t; i < M4; i += stride) {
            int4 a = p[i];
            int p0 = atomicAdd(&g_cursor[a.x], 1);
            int p1 = atomicAdd(&g_cursor[a.y], 1);
            int p2 = atomicAdd(&g_cursor[a.z], 1);
            int p3 = atomicAdd(&g_cursor[a.w], 1);
            int base = 4 * i;
            g_perm[p0] = base;
            g_perm[p1] = base + 1;
            g_perm[p2] = base + 2;
            g_perm[p3] = base + 3;
        }
    }
    for (int i = M4 * 4 + t; i < M; i += stride) {
        int id = load_id(ids, i, is64);
        g_perm[atomicAdd(&g_cursor[id], 1)] = i;
    }
}

// One warp per node; D == 128 (32 float4 per row, 1 per lane).
// Warp-cooperative index staging: one coalesced LDG fetches 32 perm indices,
// __shfl distributes them, then row loads issue in 4-wide independent batches.
__global__ void gather_kernel(const float4* __restrict__ msgs4,
                              float* __restrict__ out, int N) {
    int gw   = (blockIdx.x * blockDim.x + threadIdx.x) >> 5;
    int lane = threadIdx.x & 31;
    if (gw >= N) return;

    int cnt   = g_count[gw];
    int start = g_start[gw];

    float4 a0 = make_float4(0.f, 0.f, 0.f, 0.f);
    float4 a1 = a0, a2 = a0, a3 = a0;

    for (int c0 = 0; c0 < cnt; c0 += 32) {
        int chunk = cnt - c0; if (chunk > 32) chunk = 32;
        int pidx = (lane < chunk) ? g_perm[start + c0 + lane] : 0;  // 1 coalesced LDG
        int j = 0;
        for (; j + 4 <= chunk; j += 4) {
            int i0 = __shfl_sync(0xffffffffu, pidx, j);
            int i1 = __shfl_sync(0xffffffffu, pidx, j + 1);
            int i2 = __shfl_sync(0xffffffffu, pidx, j + 2);
            int i3 = __shfl_sync(0xffffffffu, pidx, j + 3);
            float4 v0 = __ldg(&msgs4[(size_t)i0 * 32 + lane]);
            float4 v1 = __ldg(&msgs4[(size_t)i1 * 32 + lane]);
            float4 v2 = __ldg(&msgs4[(size_t)i2 * 32 + lane]);
            float4 v3 = __ldg(&msgs4[(size_t)i3 * 32 + lane]);
            a0.x += v0.x; a0.y += v0.y; a0.z += v0.z; a0.w += v0.w;
            a1.x += v1.x; a1.y += v1.y; a1.z += v1.z; a1.w += v1.w;
            a2.x += v2.x; a2.y += v2.y; a2.z += v2.z; a2.w += v2.w;
            a3.x += v3.x; a3.y += v3.y; a3.z += v3.z; a3.w += v3.w;
        }
        for (; j < chunk; j++) {
            int i0 = __shfl_sync(0xffffffffu, pidx, j);
            float4 v = __ldg(&msgs4[(size_t)i0 * 32 + lane]);
            a0.x += v.x; a0.y += v.y; a0.z += v.z; a0.w += v.w;
        }
    }

    a0.x += a1.x + a2.x + a3.x;
    a0.y += a1.y + a2.y + a3.y;
    a0.z += a1.z + a2.z + a3.z;
    a0.w += a1.w + a2.w + a3.w;

    float inv = (cnt > 0) ? (1.0f / (float)cnt) : 0.0f;
    a0.x *= inv; a0.y *= inv; a0.z *= inv; a0.w *= inv;
    ((float4*)out)[(size_t)gw * 32 + lane] = a0;
}

// ---------- fallback path (generic D / oversized shapes) ----------
__device__ __forceinline__ void red_add_v4(float* addr, float4 v) {
    asm volatile("red.global.add.v4.f32 [%0], {%1, %2, %3, %4};"
                 :: "l"(addr), "f"(v.x), "f"(v.y), "f"(v.z), "f"(v.w) : "memory");
}
__device__ __forceinline__ void red_add_f32(float* addr, float v) {
    asm volatile("red.global.add.f32 [%0], %1;"
                 :: "l"(addr), "f"(v) : "memory");
}

__global__ void fb_init_kernel(float* __restrict__ sums, float* __restrict__ ids_out,
                               int N, int D, int has_ids) {
    long long total = (long long)N * D;
    for (long long i = blockIdx.x * (long long)blockDim.x + threadIdx.x;
         i < total; i += (long long)gridDim.x * blockDim.x)
        sums[i] = 0.f;
    for (long long i = blockIdx.x * (long long)blockDim.x + threadIdx.x;
         i < N; i += (long long)gridDim.x * blockDim.x) {
        if (i < MAX_NODES) g_fcounts[i] = 0.f;
        if (has_ids) ids_out[i] = (float)i;
    }
}

__global__ void fb_scatter_kernel(const void* __restrict__ ids,
                                  const float* __restrict__ msgs,
                                  float* __restrict__ sums, int M, int D) {
    int gwarp = (blockIdx.x * blockDim.x + threadIdx.x) >> 5;
    int lane  = threadIdx.x & 31;
    if (gwarp >= M) return;
    int id = load_id(ids, gwarp, g_is64 != 0);
    const float* row = msgs + (size_t)gwarp * D;
    float* dst = sums + (size_t)id * D;
    for (int c = lane * 4; c + 3 < D; c += 128)
        red_add_v4(dst + c, *(const float4*)(row + c));
    for (int c = (D / 4) * 4 + lane; c < D; c += 32)
        red_add_f32(dst + c, row[c]);
    if (lane == 0) red_add_f32(&g_fcounts[id], 1.0f);
}

__global__ void fb_normalize_kernel(float* __restrict__ sums, int N, int D) {
    long long total = (long long)N * D;
    for (long long i = blockIdx.x * (long long)blockDim.x + threadIdx.x;
         i < total; i += (long long)gridDim.x * blockDim.x) {
        int row = (int)(i / D);
        float inv = 1.0f / fmaxf(g_fcounts[row], 1.0f);
        sums[i] *= inv;
    }
}

extern "C" void kernel_launch(void* const* d_in, const int* in_sizes, int n_in,
                              void* d_out, int out_size) {
    const void*  ids  = d_in[0];
    const float* msgs = (const float*)d_in[1];

    int M = in_sizes[0];
    int D = in_sizes[1] / M;   // 128

    int N, has_ids;
    if (out_size % (D + 1) == 0) { N = out_size / (D + 1); has_ids = 1; }
    else                          { N = out_size / D;       has_ids = 0; }

    float* out     = (float*)d_out;
    float* ids_out = out;
    float* sums    = has_ids ? (out + N) : out;

    detect_kernel<<<1, 256>>>((const unsigned int*)ids, M);

    int nb = (N + SCAN_TILE - 1) / SCAN_TILE;
    bool fast = (D == 128) && (N <= MAX_NODES) && (M <= PERM_CAP) && (nb <= 1024);

    if (fast) {
        {
            int blocks = (N + 255) / 256; if (blocks > 2048) blocks = 2048;
            init_kernel<<<blocks, 256>>>(ids_out, N, has_ids);
        }
        {
            int blocks = (M / 4 + 255) / 256; if (blocks > 2048) blocks = 2048;
            if (blocks < 1) blocks = 1;
            hist_kernel<<<blocks, 256>>>(ids, M);
        }
        scan_partial<<<nb, 1024>>>(N);
        scan_tops<<<1, 1024>>>(nb);
        scan_final<<<nb, 1024>>>(N);
        {
            int blocks = (M / 4 + 255) / 256; if (blocks > 2048) blocks = 2048;
            if (blocks < 1) blocks = 1;
            build_perm_kernel<<<blocks, 256>>>(ids, M);
        }
        {
            long long threads = (long long)N * 32;
            int blocks = (int)((threads + 255) / 256);
            gather_kernel<<<blocks, 256>>>((const float4*)msgs, sums, N);
        }
    } else {
        {
            long long total = (long long)N * D;
            int blocks = (int)((total + 255) / 256); if (blocks > 4096) blocks = 4096;
            fb_init_kernel<<<blocks, 256>>>(sums, ids_out, N, D, has_ids);
        }
        {
            long long threads = (long long)M * 32;
            int blocks = (int)((threads + 255) / 256);
            fb_scatter_kernel<<<blocks, 256>>>(ids, msgs, sums, M, D);
        }
        {
            long long total = (long long)N * D;
            int blocks = (int)((total + 255) / 256); if (blocks > 4096) blocks = 4096;
            fb_normalize_kernel<<<blocks, 256>>>(sums, N, D);
        }
    }
}

// round 9
// speedup vs baseline: 1.1343x; 1.1343x over previous
#include <cuda_runtime.h>
#include <cuda_bf16.h>
#include <stdint.h>

// Scatter-mean via counting-sort + gather (no atomics in the hot loop).
// Pipeline: detect -> init -> rank (hist + rank-within-node, the ONLY atomic
// pass) -> 3-stage scan -> place (atomic-free perm) -> gather (2-deep pipeline).
// Fallback to a direct-atomic path for shapes exceeding static scratch.

#define MAX_NODES (1 << 20)
#define PERM_CAP  (1 << 21)
#define SCAN_TILE 4096
#define MAX_SCAN_BLOCKS ((MAX_NODES + SCAN_TILE - 1) / SCAN_TILE)

__device__ int g_is64;
__device__ int g_count[MAX_NODES];
__device__ int g_start[MAX_NODES];
__device__ int g_rank[PERM_CAP];
__device__ int g_perm[PERM_CAP];
__device__ int g_bsum[MAX_SCAN_BLOCKS];
__device__ int g_boff[MAX_SCAN_BLOCKS];
__device__ float g_fcounts[MAX_NODES];   // fallback path only

// ---------- dtype detect ----------
__global__ void detect_kernel(const unsigned int* __restrict__ words, int M) {
    __shared__ int any_nonzero;
    if (threadIdx.x == 0) any_nonzero = 0;
    __syncthreads();
    int n = (M / 2) < 4096 ? (M / 2) : 4096;
    for (int i = threadIdx.x; i < n; i += blockDim.x)
        if (words[2 * i + 1] != 0u) any_nonzero = 1;   // int64 high word
    __syncthreads();
    if (threadIdx.x == 0) g_is64 = any_nonzero ? 0 : 1;
}

__device__ __forceinline__ int load_id(const void* ids, int i, bool is64) {
    return is64 ? (int)((const long long*)ids)[i] : ((const int*)ids)[i];
}

// ---------- fast path ----------
__global__ void init_kernel(float* __restrict__ ids_out, int N, int has_ids) {
    int i = blockIdx.x * blockDim.x + threadIdx.x;
    int stride = gridDim.x * blockDim.x;
    for (; i < N; i += stride) {
        g_count[i] = 0;
        if (has_ids) ids_out[i] = (float)i;
    }
}

// Histogram + rank-within-node: the only returning-atomic pass.
// 4 independent atomic chains in flight per thread-iteration.
__global__ void rank_kernel(const void* __restrict__ ids, int M) {
    bool is64 = g_is64;
    int t = blockIdx.x * blockDim.x + threadIdx.x;
    int stride = gridDim.x * blockDim.x;
    int M4 = M >> 2;
    if (is64) {
        const longlong2* p = (const longlong2*)ids;
        for (int i = t; i < M4; i += stride) {
            longlong2 a = p[2 * i], b = p[2 * i + 1];
            int r0 = atomicAdd(&g_count[(int)a.x], 1);
            int r1 = atomicAdd(&g_count[(int)a.y], 1);
            int r2 = atomicAdd(&g_count[(int)b.x], 1);
            int r3 = atomicAdd(&g_count[(int)b.y], 1);
            int4 r = make_int4(r0, r1, r2, r3);
            ((int4*)g_rank)[i] = r;
        }
    } else {
        const int4* p = (const int4*)ids;
        for (int i = t; i < M4; i += stride) {
            int4 a = p[i];
            int r0 = atomicAdd(&g_count[a.x], 1);
            int r1 = atomicAdd(&g_count[a.y], 1);
            int r2 = atomicAdd(&g_count[a.z], 1);
            int r3 = atomicAdd(&g_count[a.w], 1);
            int4 r = make_int4(r0, r1, r2, r3);
            ((int4*)g_rank)[i] = r;
        }
    }
    for (int i = M4 * 4 + t; i < M; i += stride)
        g_rank[i] = atomicAdd(&g_count[load_id(ids, i, is64)], 1);
}

// ----- 3-stage scan: partial sums -> scan of block sums -> final rescan -----
__global__ void scan_partial(int N) {
    __shared__ int wsum[32];
    int b = blockIdx.x, tid = threadIdx.x;
    int lane = tid & 31, warp = tid >> 5;
    int base = b * SCAN_TILE + tid * 4;
    int s = 0;
    #pragma unroll
    for (int k = 0; k < 4; k++) {
        int i = base + k;
        if (i < N) s += g_count[i];
    }
    #pragma unroll
    for (int o = 16; o > 0; o >>= 1) s += __shfl_down_sync(0xffffffffu, s, o);
    if (lane == 0) wsum[warp] = s;
    __syncthreads();
    if (warp == 0) {
        int w = wsum[lane];
        #pragma unroll
        for (int o = 16; o > 0; o >>= 1) w += __shfl_down_sync(0xffffffffu, w, o);
        if (lane == 0) g_bsum[b] = w;
    }
}

__global__ void scan_tops(int nb) {   // 1 block, nb <= 1024
    __shared__ int wsum[32];
    int tid = threadIdx.x, lane = tid & 31, warp = tid >> 5;
    int s = (tid < nb) ? g_bsum[tid] : 0;
    int x = s;
    #pragma unroll
    for (int o = 1; o < 32; o <<= 1) {
        int y = __shfl_up_sync(0xffffffffu, x, o);
        if (lane >= o) x += y;
    }
    if (lane == 31) wsum[warp] = x;
    __syncthreads();
    if (warp == 0) {
        int w = wsum[lane];
        #pragma unroll
        for (int o = 1; o < 32; o <<= 1) {
            int y = __shfl_up_sync(0xffffffffu, w, o);
            if (lane >= o) w += y;
        }
        wsum[lane] = w;
    }
    __syncthreads();
    if (tid < nb) g_boff[tid] = x - s + (warp > 0 ? wsum[warp - 1] : 0);
}

__global__ void scan_final(int N) {
    __shared__ int wsum[32];
    __shared__ int boff;
    int b = blockIdx.x, tid = threadIdx.x;
    int lane = tid & 31, warp = tid >> 5;
    if (tid == 0) boff = g_boff[b];
    int base = b * SCAN_TILE + tid * 4;
    int v[4]; int s = 0;
    #pragma unroll
    for (int k = 0; k < 4; k++) {
        int i = base + k;
        v[k] = (i < N) ? g_count[i] : 0;
        s += v[k];
    }
    int x = s;
    #pragma unroll
    for (int o = 1; o < 32; o <<= 1) {
        int y = __shfl_up_sync(0xffffffffu, x, o);
        if (lane >= o) x += y;
    }
    if (lane == 31) wsum[warp] = x;
    __syncthreads();
    if (warp == 0) {
        int w = wsum[lane];
        #pragma unroll
        for (int o = 1; o < 32; o <<= 1) {
            int y = __shfl_up_sync(0xffffffffu, w, o);
            if (lane >= o) w += y;
        }
        wsum[lane] = w;
    }
    __syncthreads();
    int run = x - s + (warp > 0 ? wsum[warp - 1] : 0) + boff;
    #pragma unroll
    for (int k = 0; k < 4; k++) {
        int i = base + k;
        if (i < N) {
            g_start[i] = run;
            run += v[k];
        }
    }
}

// Atomic-free permutation: perm[start[id] + rank[i]] = i.
__global__ void place_kernel(const void* __restrict__ ids, int M) {
    bool is64 = g_is64;
    int t = blockIdx.x * blockDim.x + threadIdx.x;
    int stride = gridDim.x * blockDim.x;
    int M4 = M >> 2;
    if (is64) {
        const longlong2* p = (const longlong2*)ids;
        for (int i = t; i < M4; i += stride) {
            longlong2 a = p[2 * i], b = p[2 * i + 1];
            int4 r = ((const int4*)g_rank)[i];
            int base = 4 * i;
            g_perm[g_start[(int)a.x] + r.x] = base;
            g_perm[g_start[(int)a.y] + r.y] = base + 1;
            g_perm[g_start[(int)b.x] + r.z] = base + 2;
            g_perm[g_start[(int)b.y] + r.w] = base + 3;
        }
    } else {
        const int4* p = (const int4*)ids;
        for (int i = t; i < M4; i += stride) {
            int4 a = p[i];
            int4 r = ((const int4*)g_rank)[i];
            int base = 4 * i;
            g_perm[g_start[a.x] + r.x] = base;
            g_perm[g_start[a.y] + r.y] = base + 1;
            g_perm[g_start[a.z] + r.z] = base + 2;
            g_perm[g_start[a.w] + r.w] = base + 3;
        }
    }
    for (int i = M4 * 4 + t; i < M; i += stride) {
        int id = load_id(ids, i, is64);
        g_perm[g_start[id] + g_rank[i]] = i;
    }
}

// One warp per node; D == 128 (32 float4 per row, 1 per lane), 2-deep pipeline.
__global__ void gather_kernel(const float4* __restrict__ msgs4,
                              float* __restrict__ out, int N) {
    int gw   = (blockIdx.x * blockDim.x + threadIdx.x) >> 5;
    int lane = threadIdx.x & 31;
    if (gw >= N) return;

    int cnt   = g_count[gw];
    int start = g_start[gw];
    float4 acc = make_float4(0.f, 0.f, 0.f, 0.f);

    if (cnt > 0) {
        int idx  = g_perm[start];
        int idxn = (cnt > 1) ? g_perm[start + 1] : 0;
        float4 v = __ldg(&msgs4[(size_t)idx * 32 + lane]);
        for (int j = 1; j < cnt; j++) {
            int idxn2 = (j + 1 < cnt) ? g_perm[start + j + 1] : 0;
            float4 v2 = __ldg(&msgs4[(size_t)idxn * 32 + lane]);
            acc.x += v.x; acc.y += v.y; acc.z += v.z; acc.w += v.w;
            v = v2; idxn = idxn2;
        }
        acc.x += v.x; acc.y += v.y; acc.z += v.z; acc.w += v.w;
    }

    float inv = (cnt > 0) ? (1.0f / (float)cnt) : 0.0f;
    acc.x *= inv; acc.y *= inv; acc.z *= inv; acc.w *= inv;
    ((float4*)out)[(size_t)gw * 32 + lane] = acc;
}

// ---------- fallback path (generic D / oversized shapes) ----------
__device__ __forceinline__ void red_add_v4(float* addr, float4 v) {
    asm volatile("red.global.add.v4.f32 [%0], {%1, %2, %3, %4};"
                 :: "l"(addr), "f"(v.x), "f"(v.y), "f"(v.z), "f"(v.w) : "memory");
}
__device__ __forceinline__ void red_add_f32(float* addr, float v) {
    asm volatile("red.global.add.f32 [%0], %1;"
                 :: "l"(addr), "f"(v) : "memory");
}

__global__ void fb_init_kernel(float* __restrict__ sums, float* __restrict__ ids_out,
                               int N, int D, int has_ids) {
    long long total = (long long)N * D;
    for (long long i = blockIdx.x * (long long)blockDim.x + threadIdx.x;
         i < total; i += (long long)gridDim.x * blockDim.x)
        sums[i] = 0.f;
    for (long long i = blockIdx.x * (long long)blockDim.x + threadIdx.x;
         i < N; i += (long long)gridDim.x * blockDim.x) {
        if (i < MAX_NODES) g_fcounts[i] = 0.f;
        if (has_ids) ids_out[i] = (float)i;
    }
}

__global__ void fb_scatter_kernel(const void* __restrict__ ids,
                                  const float* __restrict__ msgs,
                                  float* __restrict__ sums, int M, int D) {
    int gwarp = (blockIdx.x * blockDim.x + threadIdx.x) >> 5;
    int lane  = threadIdx.x & 31;
    if (gwarp >= M) return;
    int id = load_id(ids, gwarp, g_is64 != 0);
    const float* row = msgs + (size_t)gwarp * D;
    float* dst = sums + (size_t)id * D;
    for (int c = lane * 4; c + 3 < D; c += 128)
        red_add_v4(dst + c, *(const float4*)(row + c));
    for (int c = (D / 4) * 4 + lane; c < D; c += 32)
        red_add_f32(dst + c, row[c]);
    if (lane == 0) red_add_f32(&g_fcounts[id], 1.0f);
}

__global__ void fb_normalize_kernel(float* __restrict__ sums, int N, int D) {
    long long total = (long long)N * D;
    for (long long i = blockIdx.x * (long long)blockDim.x + threadIdx.x;
         i < total; i += (long long)gridDim.x * blockDim.x) {
        int row = (int)(i / D);
        float inv = 1.0f / fmaxf(g_fcounts[row], 1.0f);
        sums[i] *= inv;
    }
}

extern "C" void kernel_launch(void* const* d_in, const int* in_sizes, int n_in,
                              void* d_out, int out_size) {
    const void*  ids  = d_in[0];
    const float* msgs = (const float*)d_in[1];

    int M = in_sizes[0];
    int D = in_sizes[1] / M;   // 128

    int N, has_ids;
    if (out_size % (D + 1) == 0) { N = out_size / (D + 1); has_ids = 1; }
    else                          { N = out_size / D;       has_ids = 0; }

    float* out     = (float*)d_out;
    float* ids_out = out;
    float* sums    = has_ids ? (out + N) : out;

    detect_kernel<<<1, 256>>>((const unsigned int*)ids, M);

    int nb = (N + SCAN_TILE - 1) / SCAN_TILE;
    bool fast = (D == 128) && (N <= MAX_NODES) && (M <= PERM_CAP) && (nb <= 1024);

    if (fast) {
        {
            int blocks = (N + 255) / 256; if (blocks > 2048) blocks = 2048;
            init_kernel<<<blocks, 256>>>(ids_out, N, has_ids);
        }
        {
            int blocks = (M / 4 + 255) / 256; if (blocks > 2048) blocks = 2048;
            if (blocks < 1) blocks = 1;
            rank_kernel<<<blocks, 256>>>(ids, M);
        }
        scan_partial<<<nb, 1024>>>(N);
        scan_tops<<<1, 1024>>>(nb);
        scan_final<<<nb, 1024>>>(N);
        {
            int blocks = (M / 4 + 255) / 256; if (blocks > 2048) blocks = 2048;
            if (blocks < 1) blocks = 1;
            place_kernel<<<blocks, 256>>>(ids, M);
        }
        {
            long long threads = (long long)N * 32;
            int blocks = (int)((threads + 255) / 256);
            gather_kernel<<<blocks, 256>>>((const float4*)msgs, sums, N);
        }
    } else {
        {
            long long total = (long long)N * D;
            int blocks = (int)((total + 255) / 256); if (blocks > 4096) blocks = 4096;
            fb_init_kernel<<<blocks, 256>>>(sums, ids_out, N, D, has_ids);
        }
        {
            long long threads = (long long)M * 32;
            int blocks = (int)((threads + 255) / 256);
            fb_scatter_kernel<<<blocks, 256>>>(ids, msgs, sums, M, D);
        }
        {
            long long total = (long long)N * D;
            int blocks = (int)((total + 255) / 256); if (blocks > 4096) blocks = 4096;
            fb_normalize_kernel<<<blocks, 256>>>(sums, N, D);
        }
    }
}

// round 10
// speedup vs baseline: 1.1436x; 1.0082x over previous
#include <cuda_runtime.h>
#include <cuda_bf16.h>
#include <stdint.h>

// Scatter-mean via counting-sort + gather (no atomics in the hot loop).
// Pipeline (6 launches): detect -> rank (hist + rank-within-node, only atomic
// pass) -> scan_partial -> scan_final (inline tops) -> place (atomic-free) ->
// gather (2-deep pipeline; also writes iota ids and re-zeroes g_count for the
// next graph replay -- BSS starts zeroed, so every execution sees zeroed counts).
// Fallback to a direct-atomic path for shapes exceeding static scratch.

#define MAX_NODES (1 << 20)
#define PERM_CAP  (1 << 21)
#define SCAN_TILE 4096
#define MAX_SCAN_BLOCKS ((MAX_NODES + SCAN_TILE - 1) / SCAN_TILE)

__device__ int g_is64;
__device__ int g_count[MAX_NODES];       // zero at entry of every execution
__device__ int g_start[MAX_NODES];
__device__ int g_rank[PERM_CAP];
__device__ int g_perm[PERM_CAP];
__device__ int g_bsum[MAX_SCAN_BLOCKS];
__device__ float g_fcounts[MAX_NODES];   // fallback path only

// ---------- dtype detect ----------
__global__ void detect_kernel(const unsigned int* __restrict__ words, int M) {
    __shared__ int any_nonzero;
    if (threadIdx.x == 0) any_nonzero = 0;
    __syncthreads();
    int n = (M / 2) < 4096 ? (M / 2) : 4096;
    for (int i = threadIdx.x; i < n; i += blockDim.x)
        if (words[2 * i + 1] != 0u) any_nonzero = 1;   // int64 high word
    __syncthreads();
    if (threadIdx.x == 0) g_is64 = any_nonzero ? 0 : 1;
}

__device__ __forceinline__ int load_id(const void* ids, int i, bool is64) {
    return is64 ? (int)((const long long*)ids)[i] : ((const int*)ids)[i];
}

// Histogram + rank-within-node: the only returning-atomic pass.
// 4 independent atomic chains in flight per thread-iteration.
__global__ void rank_kernel(const void* __restrict__ ids, int M) {
    bool is64 = g_is64;
    int t = blockIdx.x * blockDim.x + threadIdx.x;
    int stride = gridDim.x * blockDim.x;
    int M4 = M >> 2;
    if (is64) {
        const longlong2* p = (const longlong2*)ids;
        for (int i = t; i < M4; i += stride) {
            longlong2 a = p[2 * i], b = p[2 * i + 1];
            int r0 = atomicAdd(&g_count[(int)a.x], 1);
            int r1 = atomicAdd(&g_count[(int)a.y], 1);
            int r2 = atomicAdd(&g_count[(int)b.x], 1);
            int r3 = atomicAdd(&g_count[(int)b.y], 1);
            ((int4*)g_rank)[i] = make_int4(r0, r1, r2, r3);
        }
    } else {
        const int4* p = (const int4*)ids;
        for (int i = t; i < M4; i += stride) {
            int4 a = p[i];
            int r0 = atomicAdd(&g_count[a.x], 1);
            int r1 = atomicAdd(&g_count[a.y], 1);
            int r2 = atomicAdd(&g_count[a.z], 1);
            int r3 = atomicAdd(&g_count[a.w], 1);
            ((int4*)g_rank)[i] = make_int4(r0, r1, r2, r3);
        }
    }
    for (int i = M4 * 4 + t; i < M; i += stride)
        g_rank[i] = atomicAdd(&g_count[load_id(ids, i, is64)], 1);
}

// ----- 2-stage scan: partial sums -> final rescan with inline tops scan -----
__global__ void scan_partial(int N) {
    __shared__ int wsum[32];
    int b = blockIdx.x, tid = threadIdx.x;
    int lane = tid & 31, warp = tid >> 5;
    int base = b * SCAN_TILE + tid * 4;
    int s = 0;
    #pragma unroll
    for (int k = 0; k < 4; k++) {
        int i = base + k;
        if (i < N) s += g_count[i];
    }
    #pragma unroll
    for (int o = 16; o > 0; o >>= 1) s += __shfl_down_sync(0xffffffffu, s, o);
    if (lane == 0) wsum[warp] = s;
    __syncthreads();
    if (warp == 0) {
        int w = wsum[lane];
        #pragma unroll
        for (int o = 16; o > 0; o >>= 1) w += __shfl_down_sync(0xffffffffu, w, o);
        if (lane == 0) g_bsum[b] = w;
    }
}

__global__ void scan_final(int N, int nb) {
    __shared__ int wsum[32];
    __shared__ int sboff[1024];
    int b = blockIdx.x, tid = threadIdx.x;
    int lane = tid & 31, warp = tid >> 5;

    // Inline exclusive scan of the nb block sums (nb <= 1024).
    {
        int s = (tid < nb) ? g_bsum[tid] : 0;
        int x = s;
        #pragma unroll
        for (int o = 1; o < 32; o <<= 1) {
            int y = __shfl_up_sync(0xffffffffu, x, o);
            if (lane >= o) x += y;
        }
        if (lane == 31) wsum[warp] = x;
        __syncthreads();
        if (warp == 0) {
            int w = wsum[lane];
            #pragma unroll
            for (int o = 1; o < 32; o <<= 1) {
                int y = __shfl_up_sync(0xffffffffu, w, o);
                if (lane >= o) w += y;
            }
            wsum[lane] = w;
        }
        __syncthreads();
        if (tid < nb) sboff[tid] = x - s + (warp > 0 ? wsum[warp - 1] : 0);
        __syncthreads();
    }
    int boff = sboff[b];
    __syncthreads();   // wsum reuse below

    int base = b * SCAN_TILE + tid * 4;
    int v[4]; int s = 0;
    #pragma unroll
    for (int k = 0; k < 4; k++) {
        int i = base + k;
        v[k] = (i < N) ? g_count[i] : 0;
        s += v[k];
    }
    int x = s;
    #pragma unroll
    for (int o = 1; o < 32; o <<= 1) {
        int y = __shfl_up_sync(0xffffffffu, x, o);
        if (lane >= o) x += y;
    }
    if (lane == 31) wsum[warp] = x;
    __syncthreads();
    if (warp == 0) {
        int w = wsum[lane];
        #pragma unroll
        for (int o = 1; o < 32; o <<= 1) {
            int y = __shfl_up_sync(0xffffffffu, w, o);
            if (lane >= o) w += y;
        }
        wsum[lane] = w;
    }
    __syncthreads();
    int run = x - s + (warp > 0 ? wsum[warp - 1] : 0) + boff;
    #pragma unroll
    for (int k = 0; k < 4; k++) {
        int i = base + k;
        if (i < N) {
            g_start[i] = run;
            run += v[k];
        }
    }
}

// Atomic-free permutation: perm[start[id] + rank[i]] = i.
__global__ void place_kernel(const void* __restrict__ ids, int M) {
    bool is64 = g_is64;
    int t = blockIdx.x * blockDim.x + threadIdx.x;
    int stride = gridDim.x * blockDim.x;
    int M4 = M >> 2;
    if (is64) {
        const longlong2* p = (const longlong2*)ids;
        for (int i = t; i < M4; i += stride) {
            longlong2 a = p[2 * i], b = p[2 * i + 1];
            int4 r = ((const int4*)g_rank)[i];
            int base = 4 * i;
            g_perm[g_start[(int)a.x] + r.x] = base;
            g_perm[g_start[(int)a.y] + r.y] = base + 1;
            g_perm[g_start[(int)b.x] + r.z] = base + 2;
            g_perm[g_start[(int)b.y] + r.w] = base + 3;
        }
    } else {
        const int4* p = (const int4*)ids;
        for (int i = t; i < M4; i += stride) {
            int4 a = p[i];
            int4 r = ((const int4*)g_rank)[i];
            int base = 4 * i;
            g_perm[g_start[a.x] + r.x] = base;
            g_perm[g_start[a.y] + r.y] = base + 1;
            g_perm[g_start[a.z] + r.z] = base + 2;
            g_perm[g_start[a.w] + r.w] = base + 3;
        }
    }
    for (int i = M4 * 4 + t; i < M; i += stride) {
        int id = load_id(ids, i, is64);
        g_perm[g_start[id] + g_rank[i]] = i;
    }
}

// One warp per node; D == 128 (32 float4 per row, 1 per lane), 2-deep pipeline.
// Also writes iota ids output and re-zeroes g_count for the next execution.
__global__ void gather_kernel(const float4* __restrict__ msgs4,
                              float* __restrict__ out,
                              float* __restrict__ ids_out,
                              int N, int has_ids) {
    int gw   = (blockIdx.x * blockDim.x + threadIdx.x) >> 5;
    int lane = threadIdx.x & 31;
    if (gw >= N) return;

    int cnt   = g_count[gw];
    int start = g_start[gw];
    float4 acc = make_float4(0.f, 0.f, 0.f, 0.f);

    if (cnt > 0) {
        int idx  = g_perm[start];
        int idxn = (cnt > 1) ? g_perm[start + 1] : 0;
        float4 v = __ldg(&msgs4[(size_t)idx * 32 + lane]);
        for (int j = 1; j < cnt; j++) {
            int idxn2 = (j + 1 < cnt) ? g_perm[start + j + 1] : 0;
            float4 v2 = __ldg(&msgs4[(size_t)idxn * 32 + lane]);
            acc.x += v.x; acc.y += v.y; acc.z += v.z; acc.w += v.w;
            v = v2; idxn = idxn2;
        }
        acc.x += v.x; acc.y += v.y; acc.z += v.z; acc.w += v.w;
    }

    float inv = (cnt > 0) ? (1.0f / (float)cnt) : 0.0f;
    acc.x *= inv; acc.y *= inv; acc.z *= inv; acc.w *= inv;
    ((float4*)out)[(size_t)gw * 32 + lane] = acc;

    if (lane == 0) g_count[gw] = 0;                      // zero for next execution
    if (lane == 1 && has_ids) ids_out[gw] = (float)gw;   // iota ids output
}

// ---------- fallback path (generic D / oversized shapes) ----------
__device__ __forceinline__ void red_add_v4(float* addr, float4 v) {
    asm volatile("red.global.add.v4.f32 [%0], {%1, %2, %3, %4};"
                 :: "l"(addr), "f"(v.x), "f"(v.y), "f"(v.z), "f"(v.w) : "memory");
}
__device__ __forceinline__ void red_add_f32(float* addr, float v) {
    asm volatile("red.global.add.f32 [%0], %1;"
                 :: "l"(addr), "f"(v) : "memory");
}

__global__ void fb_init_kernel(float* __restrict__ sums, float* __restrict__ ids_out,
                               int N, int D, int has_ids) {
    long long total = (long long)N * D;
    for (long long i = blockIdx.x * (long long)blockDim.x + threadIdx.x;
         i < total; i += (long long)gridDim.x * blockDim.x)
        sums[i] = 0.f;
    for (long long i = blockIdx.x * (long long)blockDim.x + threadIdx.x;
         i < N; i += (long long)gridDim.x * blockDim.x) {
        if (i < MAX_NODES) g_fcounts[i] = 0.f;
        if (has_ids) ids_out[i] = (float)i;
    }
}

__global__ void fb_scatter_kernel(const void* __restrict__ ids,
                                  const float* __restrict__ msgs,
                                  float* __restrict__ sums, int M, int D) {
    int gwarp = (blockIdx.x * blockDim.x + threadIdx.x) >> 5;
    int lane  = threadIdx.x & 31;
    if (gwarp >= M) return;
    int id = load_id(ids, gwarp, g_is64 != 0);
    const float* row = msgs + (size_t)gwarp * D;
    float* dst = sums + (size_t)id * D;
    for (int c = lane * 4; c + 3 < D; c += 128)
        red_add_v4(dst + c, *(const float4*)(row + c));
    for (int c = (D / 4) * 4 + lane; c < D; c += 32)
        red_add_f32(dst + c, row[c]);
    if (lane == 0) red_add_f32(&g_fcounts[id], 1.0f);
}

__global__ void fb_normalize_kernel(float* __restrict__ sums, int N, int D) {
    long long total = (long long)N * D;
    for (long long i = blockIdx.x * (long long)blockDim.x + threadIdx.x;
         i < total; i += (long long)gridDim.x * blockDim.x) {
        int row = (int)(i / D);
        float inv = 1.0f / fmaxf(g_fcounts[row], 1.0f);
        sums[i] *= inv;
    }
}

extern "C" void kernel_launch(void* const* d_in, const int* in_sizes, int n_in,
                              void* d_out, int out_size) {
    const void*  ids  = d_in[0];
    const float* msgs = (const float*)d_in[1];

    int M = in_sizes[0];
    int D = in_sizes[1] / M;   // 128

    int N, has_ids;
    if (out_size % (D + 1) == 0) { N = out_size / (D + 1); has_ids = 1; }
    else                          { N = out_size / D;       has_ids = 0; }

    float* out     = (float*)d_out;
    float* ids_out = out;
    float* sums    = has_ids ? (out + N) : out;

    detect_kernel<<<1, 256>>>((const unsigned int*)ids, M);

    int nb = (N + SCAN_TILE - 1) / SCAN_TILE;
    bool fast = (D == 128) && (N <= MAX_NODES) && (M <= PERM_CAP) && (nb <= 1024);

    if (fast) {
        {
            int blocks = (M / 4 + 255) / 256; if (blocks > 2048) blocks = 2048;
            if (blocks < 1) blocks = 1;
            rank_kernel<<<blocks, 256>>>(ids, M);
        }
        scan_partial<<<nb, 1024>>>(N);
        scan_final<<<nb, 1024>>>(N, nb);
        {
            int blocks = (M / 4 + 255) / 256; if (blocks > 2048) blocks = 2048;
            if (blocks < 1) blocks = 1;
            place_kernel<<<blocks, 256>>>(ids, M);
        }
        {
            long long threads = (long long)N * 32;
            int blocks = (int)((threads + 255) / 256);
            gather_kernel<<<blocks, 256>>>((const float4*)msgs, sums, ids_out, N, has_ids);
        }
    } else {
        {
            long long total = (long long)N * D;
            int blocks = (int)((total + 255) / 256); if (blocks > 4096) blocks = 4096;
            fb_init_kernel<<<blocks, 256>>>(sums, ids_out, N, D, has_ids);
        }
        {
            long long threads = (long long)M * 32;
            int blocks = (int)((threads + 255) / 256);
            fb_scatter_kernel<<<blocks, 256>>>(ids, msgs, sums, M, D);
        }
        {
            long long total = (long long)N * D;
            int blocks = (int)((total + 255) / 256); if (blocks > 4096) blocks = 4096;
            fb_normalize_kernel<<<blocks, 256>>>(sums, N, D);
        }
    }
}

// round 11
// speedup vs baseline: 1.1904x; 1.0409x over previous
#include <cuda_runtime.h>
#include <cuda_bf16.h>
#include <stdint.h>

// Scatter-mean via counting-sort + gather (no atomics in the hot loop).
// Pipeline (5 launches): rank (inline dtype detect + hist + rank-within-node,
// only atomic pass) -> scan_partial -> scan_final (inline tops) -> place
// (atomic-free) -> gather (2-deep pipeline; writes iota ids, re-zeroes g_count
// for the next graph replay -- BSS starts zeroed).
// Fallback to a direct-atomic path for shapes exceeding static scratch.

#define MAX_NODES (1 << 20)
#define PERM_CAP  (1 << 21)
#define SCAN_TILE 4096
#define MAX_SCAN_BLOCKS ((MAX_NODES + SCAN_TILE - 1) / SCAN_TILE)

__device__ int g_count[MAX_NODES];       // zero at entry of every execution
__device__ int g_start[MAX_NODES];
__device__ int g_rank[PERM_CAP];
__device__ int g_perm[PERM_CAP];
__device__ int g_bsum[MAX_SCAN_BLOCKS];
__device__ float g_fcounts[MAX_NODES];   // fallback path only

// Per-block inline dtype detection: examine 256 odd-position 32-bit words from
// this block's own region. int64 ids < 2^32 have all-zero high words; int32
// random ids make some odd word nonzero with overwhelming probability. The
// degenerate all-zero case decodes identically either way.
__device__ __forceinline__ bool detect_is64_block(const unsigned int* words, int M) {
    // M words are guaranteed to exist under the int32 interpretation (and 2M
    // under int64), so any odd index < M is safe to read.
    int t = threadIdx.x & 255;
    int span = M >> 1;                 // number of (even,odd) pairs within M words
    unsigned int w = 0u;
    if (span > 0) {
        int wbase = (int)blockIdx.x * 256;
        if (span > 256) wbase %= (span - 255); else wbase = 0;
        int p = wbase + t;
        if (p < span) w = words[2 * p + 1];
    }
    return __syncthreads_or((int)w) == 0;   // all high words zero -> int64
}

__device__ __forceinline__ int load_id(const void* ids, int i, bool is64) {
    return is64 ? (int)((const long long*)ids)[i] : ((const int*)ids)[i];
}

// Histogram + rank-within-node: the only returning-atomic pass.
// 4 independent atomic chains in flight per thread-iteration.
__global__ void rank_kernel(const void* __restrict__ ids, int M) {
    bool is64 = detect_is64_block((const unsigned int*)ids, M);
    int t = blockIdx.x * blockDim.x + threadIdx.x;
    int stride = gridDim.x * blockDim.x;
    int M4 = M >> 2;
    if (is64) {
        const longlong2* p = (const longlong2*)ids;
        for (int i = t; i < M4; i += stride) {
            longlong2 a = p[2 * i], b = p[2 * i + 1];
            int r0 = atomicAdd(&g_count[(int)a.x], 1);
            int r1 = atomicAdd(&g_count[(int)a.y], 1);
            int r2 = atomicAdd(&g_count[(int)b.x], 1);
            int r3 = atomicAdd(&g_count[(int)b.y], 1);
            ((int4*)g_rank)[i] = make_int4(r0, r1, r2, r3);
        }
    } else {
        const int4* p = (const int4*)ids;
        for (int i = t; i < M4; i += stride) {
            int4 a = p[i];
            int r0 = atomicAdd(&g_count[a.x], 1);
            int r1 = atomicAdd(&g_count[a.y], 1);
            int r2 = atomicAdd(&g_count[a.z], 1);
            int r3 = atomicAdd(&g_count[a.w], 1);
            ((int4*)g_rank)[i] = make_int4(r0, r1, r2, r3);
        }
    }
    for (int i = M4 * 4 + t; i < M; i += stride)
        g_rank[i] = atomicAdd(&g_count[load_id(ids, i, is64)], 1);
}

// ----- 2-stage scan: partial sums -> final rescan with inline tops scan -----
__global__ void scan_partial(int N) {
    __shared__ int wsum[32];
    int b = blockIdx.x, tid = threadIdx.x;
    int lane = tid & 31, warp = tid >> 5;
    int base = b * SCAN_TILE + tid * 4;
    int s = 0;
    #pragma unroll
    for (int k = 0; k < 4; k++) {
        int i = base + k;
        if (i < N) s += g_count[i];
    }
    #pragma unroll
    for (int o = 16; o > 0; o >>= 1) s += __shfl_down_sync(0xffffffffu, s, o);
    if (lane == 0) wsum[warp] = s;
    __syncthreads();
    if (warp == 0) {
        int w = wsum[lane];
        #pragma unroll
        for (int o = 16; o > 0; o >>= 1) w += __shfl_down_sync(0xffffffffu, w, o);
        if (lane == 0) g_bsum[b] = w;
    }
}

__global__ void scan_final(int N, int nb) {
    __shared__ int wsum[32];
    __shared__ int sboff[1024];
    int b = blockIdx.x, tid = threadIdx.x;
    int lane = tid & 31, warp = tid >> 5;

    // Inline exclusive scan of the nb block sums (nb <= 1024).
    {
        int s = (tid < nb) ? g_bsum[tid] : 0;
        int x = s;
        #pragma unroll
        for (int o = 1; o < 32; o <<= 1) {
            int y = __shfl_up_sync(0xffffffffu, x, o);
            if (lane >= o) x += y;
        }
        if (lane == 31) wsum[warp] = x;
        __syncthreads();
        if (warp == 0) {
            int w = wsum[lane];
            #pragma unroll
            for (int o = 1; o < 32; o <<= 1) {
                int y = __shfl_up_sync(0xffffffffu, w, o);
                if (lane >= o) w += y;
            }
            wsum[lane] = w;
        }
        __syncthreads();
        if (tid < nb) sboff[tid] = x - s + (warp > 0 ? wsum[warp - 1] : 0);
        __syncthreads();
    }
    int boff = sboff[b];
    __syncthreads();   // wsum reuse below

    int base = b * SCAN_TILE + tid * 4;
    int v[4]; int s = 0;
    #pragma unroll
    for (int k = 0; k < 4; k++) {
        int i = base + k;
        v[k] = (i < N) ? g_count[i] : 0;
        s += v[k];
    }
    int x = s;
    #pragma unroll
    for (int o = 1; o < 32; o <<= 1) {
        int y = __shfl_up_sync(0xffffffffu, x, o);
        if (lane >= o) x += y;
    }
    if (lane == 31) wsum[warp] = x;
    __syncthreads();
    if (warp == 0) {
        int w = wsum[lane];
        #pragma unroll
        for (int o = 1; o < 32; o <<= 1) {
            int y = __shfl_up_sync(0xffffffffu, w, o);
            if (lane >= o) w += y;
        }
        wsum[lane] = w;
    }
    __syncthreads();
    int run = x - s + (warp > 0 ? wsum[warp - 1] : 0) + boff;
    #pragma unroll
    for (int k = 0; k < 4; k++) {
        int i = base + k;
        if (i < N) {
            g_start[i] = run;
            run += v[k];
        }
    }
}

// Atomic-free permutation: perm[start[id] + rank[i]] = i.
__global__ void place_kernel(const void* __restrict__ ids, int M) {
    bool is64 = detect_is64_block((const unsigned int*)ids, M);
    int t = blockIdx.x * blockDim.x + threadIdx.x;
    int stride = gridDim.x * blockDim.x;
    int M4 = M >> 2;
    if (is64) {
        const longlong2* p = (const longlong2*)ids;
        for (int i = t; i < M4; i += stride) {
            longlong2 a = p[2 * i], b = p[2 * i + 1];
            int4 r = ((const int4*)g_rank)[i];
            int base = 4 * i;
            g_perm[g_start[(int)a.x] + r.x] = base;
            g_perm[g_start[(int)a.y] + r.y] = base + 1;
            g_perm[g_start[(int)b.x] + r.z] = base + 2;
            g_perm[g_start[(int)b.y] + r.w] = base + 3;
        }
    } else {
        const int4* p = (const int4*)ids;
        for (int i = t; i < M4; i += stride) {
            int4 a = p[i];
            int4 r = ((const int4*)g_rank)[i];
            int base = 4 * i;
            g_perm[g_start[a.x] + r.x] = base;
            g_perm[g_start[a.y] + r.y] = base + 1;
            g_perm[g_start[a.z] + r.z] = base + 2;
            g_perm[g_start[a.w] + r.w] = base + 3;
        }
    }
    for (int i = M4 * 4 + t; i < M; i += stride) {
        int id = load_id(ids, i, is64);
        g_perm[g_start[id] + g_rank[i]] = i;
    }
}

// One warp per node; D == 128 (32 float4 per row, 1 per lane), 2-deep pipeline.
// Also writes iota ids output and re-zeroes g_count for the next execution.
__global__ void gather_kernel(const float4* __restrict__ msgs4,
                              float* __restrict__ out,
                              float* __restrict__ ids_out,
                              int N, int has_ids) {
    int gw   = (blockIdx.x * blockDim.x + threadIdx.x) >> 5;
    int lane = threadIdx.x & 31;
    if (gw >= N) return;

    int cnt   = g_count[gw];
    int start = g_start[gw];
    float4 acc = make_float4(0.f, 0.f, 0.f, 0.f);

    if (cnt > 0) {
        int idx  = g_perm[start];
        int idxn = (cnt > 1) ? g_perm[start + 1] : 0;
        float4 v = __ldg(&msgs4[(size_t)idx * 32 + lane]);
        for (int j = 1; j < cnt; j++) {
            int idxn2 = (j + 1 < cnt) ? g_perm[start + j + 1] : 0;
            float4 v2 = __ldg(&msgs4[(size_t)idxn * 32 + lane]);
            acc.x += v.x; acc.y += v.y; acc.z += v.z; acc.w += v.w;
            v = v2; idxn = idxn2;
        }
        acc.x += v.x; acc.y += v.y; acc.z += v.z; acc.w += v.w;
    }

    float inv = (cnt > 0) ? (1.0f / (float)cnt) : 0.0f;
    acc.x *= inv; acc.y *= inv; acc.z *= inv; acc.w *= inv;
    ((float4*)out)[(size_t)gw * 32 + lane] = acc;

    if (lane == 0) g_count[gw] = 0;                      // zero for next execution
    if (lane == 1 && has_ids) ids_out[gw] = (float)gw;   // iota ids output
}

// ---------- fallback path (generic D / oversized shapes) ----------
__device__ __forceinline__ void red_add_v4(float* addr, float4 v) {
    asm volatile("red.global.add.v4.f32 [%0], {%1, %2, %3, %4};"
                 :: "l"(addr), "f"(v.x), "f"(v.y), "f"(v.z), "f"(v.w) : "memory");
}
__device__ __forceinline__ void red_add_f32(float* addr, float v) {
    asm volatile("red.global.add.f32 [%0], %1;"
                 :: "l"(addr), "f"(v) : "memory");
}

__global__ void fb_init_kernel(float* __restrict__ sums, float* __restrict__ ids_out,
                               int N, int D, int has_ids) {
    long long total = (long long)N * D;
    for (long long i = blockIdx.x * (long long)blockDim.x + threadIdx.x;
         i < total; i += (long long)gridDim.x * blockDim.x)
        sums[i] = 0.f;
    for (long long i = blockIdx.x * (long long)blockDim.x + threadIdx.x;
         i < N; i += (long long)gridDim.x * blockDim.x) {
        if (i < MAX_NODES) g_fcounts[i] = 0.f;
        if (has_ids) ids_out[i] = (float)i;
    }
}

__global__ void fb_scatter_kernel(const void* __restrict__ ids,
                                  const float* __restrict__ msgs,
                                  float* __restrict__ sums, int M, int D) {
    bool is64 = detect_is64_block((const unsigned int*)ids, M);
    int gwarp = (blockIdx.x * blockDim.x + threadIdx.x) >> 5;
    int lane  = threadIdx.x & 31;
    if (gwarp >= M) return;
    int id = load_id(ids, gwarp, is64);
    const float* row = msgs + (size_t)gwarp * D;
    float* dst = sums + (size_t)id * D;
    for (int c = lane * 4; c + 3 < D; c += 128)
        red_add_v4(dst + c, *(const float4*)(row + c));
    for (int c = (D / 4) * 4 + lane; c < D; c += 32)
        red_add_f32(dst + c, row[c]);
    if (lane == 0) red_add_f32(&g_fcounts[id], 1.0f);
}

__global__ void fb_normalize_kernel(float* __restrict__ sums, int N, int D) {
    long long total = (long long)N * D;
    for (long long i = blockIdx.x * (long long)blockDim.x + threadIdx.x;
         i < total; i += (long long)gridDim.x * blockDim.x) {
        int row = (int)(i / D);
        float inv = 1.0f / fmaxf(g_fcounts[row], 1.0f);
        sums[i] *= inv;
    }
}

extern "C" void kernel_launch(void* const* d_in, const int* in_sizes, int n_in,
                              void* d_out, int out_size) {
    const void*  ids  = d_in[0];
    const float* msgs = (const float*)d_in[1];

    int M = in_sizes[0];
    int D = in_sizes[1] / M;   // 128

    int N, has_ids;
    if (out_size % (D + 1) == 0) { N = out_size / (D + 1); has_ids = 1; }
    else                          { N = out_size / D;       has_ids = 0; }

    float* out     = (float*)d_out;
    float* ids_out = out;
    float* sums    = has_ids ? (out + N) : out;

    int nb = (N + SCAN_TILE - 1) / SCAN_TILE;
    bool fast = (D == 128) && (N <= MAX_NODES) && (M <= PERM_CAP) && (nb <= 1024);

    if (fast) {
        {
            int blocks = (M / 4 + 255) / 256; if (blocks > 2048) blocks = 2048;
            if (blocks < 1) blocks = 1;
            rank_kernel<<<blocks, 256>>>(ids, M);
        }
        scan_partial<<<nb, 1024>>>(N);
        scan_final<<<nb, 1024>>>(N, nb);
        {
            int blocks = (M / 4 + 255) / 256; if (blocks > 2048) blocks = 2048;
            if (blocks < 1) blocks = 1;
            place_kernel<<<blocks, 256>>>(ids, M);
        }
        {
            long long threads = (long long)N * 32;
            int blocks = (int)((threads + 255) / 256);
            gather_kernel<<<blocks, 256>>>((const float4*)msgs, sums, ids_out, N, has_ids);
        }
    } else {
        {
            long long total = (long long)N * D;
            int blocks = (int)((total + 255) / 256); if (blocks > 4096) blocks = 4096;
            fb_init_kernel<<<blocks, 256>>>(sums, ids_out, N, D, has_ids);
        }
        {
            long long threads = (long long)M * 32;
            int blocks = (int)((threads + 255) / 256);
            fb_scatter_kernel<<<blocks, 256>>>(ids, msgs, sums, M, D);
        }
        {
            long long total = (long long)N * D;
            int blocks = (int)((total + 255) / 256); if (blocks > 4096) blocks = 4096;
            fb_normalize_kernel<<<blocks, 256>>>(sums, N, D);
        }
    }
}

// round 12
// speedup vs baseline: 1.1913x; 1.0008x over previous
#include <cuda_runtime.h>
#include <cuda_bf16.h>
#include <stdint.h>

// Scatter-mean via counting-sort + gather (no atomics in the hot loop).
// Pipeline (5 launches): rank (inline dtype detect + hist + rank-within-node,
// only atomic pass) -> scan_partial -> scan_final (inline tops) -> place
// (atomic-free, 8-wide MLP) -> gather (2-deep pipeline; writes iota ids,
// re-zeroes g_count for the next graph replay -- BSS starts zeroed).
// Fallback to a direct-atomic path for shapes exceeding static scratch.

#define MAX_NODES (1 << 20)
#define PERM_CAP  (1 << 21)
#define SCAN_TILE 1024
#define SCAN_THREADS 512
#define MAX_SCAN_BLOCKS ((MAX_NODES + SCAN_TILE - 1) / SCAN_TILE)

__device__ int g_count[MAX_NODES];       // zero at entry of every execution
__device__ int g_start[MAX_NODES];
__device__ int g_rank[PERM_CAP];
__device__ int g_perm[PERM_CAP];
__device__ int g_bsum[MAX_SCAN_BLOCKS];
__device__ float g_fcounts[MAX_NODES];   // fallback path only

// Per-block inline dtype detection: examine 256 odd-position 32-bit words from
// this block's own region. int64 ids < 2^32 have all-zero high words; int32
// random ids make some odd word nonzero with overwhelming probability. The
// degenerate all-zero case decodes identically either way.
__device__ __forceinline__ bool detect_is64_block(const unsigned int* words, int M) {
    int t = threadIdx.x & 255;
    int span = M >> 1;                 // number of (even,odd) pairs within M words
    unsigned int w = 0u;
    if (span > 0) {
        int wbase = (int)blockIdx.x * 256;
        if (span > 256) wbase %= (span - 255); else wbase = 0;
        int p = wbase + t;
        if (p < span) w = words[2 * p + 1];
    }
    return __syncthreads_or((int)w) == 0;   // all high words zero -> int64
}

__device__ __forceinline__ int load_id(const void* ids, int i, bool is64) {
    return is64 ? (int)((const long long*)ids)[i] : ((const int*)ids)[i];
}

// Histogram + rank-within-node: the only returning-atomic pass.
// 4 independent atomic chains in flight per thread-iteration.
__global__ void rank_kernel(const void* __restrict__ ids, int M) {
    bool is64 = detect_is64_block((const unsigned int*)ids, M);
    int t = blockIdx.x * blockDim.x + threadIdx.x;
    int stride = gridDim.x * blockDim.x;
    int M4 = M >> 2;
    if (is64) {
        const longlong2* p = (const longlong2*)ids;
        for (int i = t; i < M4; i += stride) {
            longlong2 a = p[2 * i], b = p[2 * i + 1];
            int r0 = atomicAdd(&g_count[(int)a.x], 1);
            int r1 = atomicAdd(&g_count[(int)a.y], 1);
            int r2 = atomicAdd(&g_count[(int)b.x], 1);
            int r3 = atomicAdd(&g_count[(int)b.y], 1);
            ((int4*)g_rank)[i] = make_int4(r0, r1, r2, r3);
        }
    } else {
        const int4* p = (const int4*)ids;
        for (int i = t; i < M4; i += stride) {
            int4 a = p[i];
            int r0 = atomicAdd(&g_count[a.x], 1);
            int r1 = atomicAdd(&g_count[a.y], 1);
            int r2 = atomicAdd(&g_count[a.z], 1);
            int r3 = atomicAdd(&g_count[a.w], 1);
            ((int4*)g_rank)[i] = make_int4(r0, r1, r2, r3);
        }
    }
    for (int i = M4 * 4 + t; i < M; i += stride)
        g_rank[i] = atomicAdd(&g_count[load_id(ids, i, is64)], 1);
}

// ----- 2-stage scan: partial sums -> final rescan with inline tops scan -----
__global__ void scan_partial(int N) {
    __shared__ int wsum[SCAN_THREADS / 32];
    int b = blockIdx.x, tid = threadIdx.x;
    int lane = tid & 31, warp = tid >> 5;
    int base = b * SCAN_TILE + tid * 2;
    int s = 0;
    #pragma unroll
    for (int k = 0; k < 2; k++) {
        int i = base + k;
        if (i < N) s += g_count[i];
    }
    #pragma unroll
    for (int o = 16; o > 0; o >>= 1) s += __shfl_down_sync(0xffffffffu, s, o);
    if (lane == 0) wsum[warp] = s;
    __syncthreads();
    if (warp == 0) {
        int w = (lane < SCAN_THREADS / 32) ? wsum[lane] : 0;
        #pragma unroll
        for (int o = 16; o > 0; o >>= 1) w += __shfl_down_sync(0xffffffffu, w, o);
        if (lane == 0) g_bsum[b] = w;
    }
}

__global__ void scan_final(int N, int nb) {
    __shared__ int wsum[32];
    __shared__ int sboff[1024];
    int b = blockIdx.x, tid = threadIdx.x;
    int lane = tid & 31, warp = tid >> 5;

    // Inline exclusive scan of the nb block sums (nb <= 1024; here 512 threads
    // handle up to 512 sums per thread 1:1 -- need nb <= SCAN_THREADS).
    {
        int s = (tid < nb) ? g_bsum[tid] : 0;
        int x = s;
        #pragma unroll
        for (int o = 1; o < 32; o <<= 1) {
            int y = __shfl_up_sync(0xffffffffu, x, o);
            if (lane >= o) x += y;
        }
        if (lane == 31) wsum[warp] = x;
        __syncthreads();
        if (warp == 0) {
            int w = (lane < SCAN_THREADS / 32) ? wsum[lane] : 0;
            #pragma unroll
            for (int o = 1; o < 32; o <<= 1) {
                int y = __shfl_up_sync(0xffffffffu, w, o);
                if (lane >= o) w += y;
            }
            wsum[lane] = w;
        }
        __syncthreads();
        if (tid < nb) sboff[tid] = x - s + (warp > 0 ? wsum[warp - 1] : 0);
        __syncthreads();
    }
    int boff = sboff[b];
    __syncthreads();   // wsum reuse below

    int base = b * SCAN_TILE + tid * 2;
    int v[2]; int s = 0;
    #pragma unroll
    for (int k = 0; k < 2; k++) {
        int i = base + k;
        v[k] = (i < N) ? g_count[i] : 0;
        s += v[k];
    }
    int x = s;
    #pragma unroll
    for (int o = 1; o < 32; o <<= 1) {
        int y = __shfl_up_sync(0xffffffffu, x, o);
        if (lane >= o) x += y;
    }
    if (lane == 31) wsum[warp] = x;
    __syncthreads();
    if (warp == 0) {
        int w = (lane < SCAN_THREADS / 32) ? wsum[lane] : 0;
        #pragma unroll
        for (int o = 1; o < 32; o <<= 1) {
            int y = __shfl_up_sync(0xffffffffu, w, o);
            if (lane >= o) w += y;
        }
        wsum[lane] = w;
    }
    __syncthreads();
    int run = x - s + (warp > 0 ? wsum[warp - 1] : 0) + boff;
    #pragma unroll
    for (int k = 0; k < 2; k++) {
        int i = base + k;
        if (i < N) {
            g_start[i] = run;
            run += v[k];
        }
    }
}

// Atomic-free permutation: perm[start[id] + rank[i]] = i.
// 8 independent load->store chains per thread-iteration.
__global__ void place_kernel(const void* __restrict__ ids, int M) {
    bool is64 = detect_is64_block((const unsigned int*)ids, M);
    int t = blockIdx.x * blockDim.x + threadIdx.x;
    int stride = gridDim.x * blockDim.x;
    int M8 = M >> 3;
    if (is64) {
        const longlong2* p = (const longlong2*)ids;
        for (int i = t; i < M8; i += stride) {
            longlong2 a = p[4 * i],     b = p[4 * i + 1];
            longlong2 c = p[4 * i + 2], d = p[4 * i + 3];
            int4 r0 = ((const int4*)g_rank)[2 * i];
            int4 r1 = ((const int4*)g_rank)[2 * i + 1];
            int s0 = g_start[(int)a.x], s1 = g_start[(int)a.y];
            int s2 = g_start[(int)b.x], s3 = g_start[(int)b.y];
            int s4 = g_start[(int)c.x], s5 = g_start[(int)c.y];
            int s6 = g_start[(int)d.x], s7 = g_start[(int)d.y];
            int base = 8 * i;
            g_perm[s0 + r0.x] = base;
            g_perm[s1 + r0.y] = base + 1;
            g_perm[s2 + r0.z] = base + 2;
            g_perm[s3 + r0.w] = base + 3;
            g_perm[s4 + r1.x] = base + 4;
            g_perm[s5 + r1.y] = base + 5;
            g_perm[s6 + r1.z] = base + 6;
            g_perm[s7 + r1.w] = base + 7;
        }
    } else {
        const int4* p = (const int4*)ids;
        for (int i = t; i < M8; i += stride) {
            int4 a = p[2 * i], b = p[2 * i + 1];
            int4 r0 = ((const int4*)g_rank)[2 * i];
            int4 r1 = ((const int4*)g_rank)[2 * i + 1];
            int s0 = g_start[a.x], s1 = g_start[a.y];
            int s2 = g_start[a.z], s3 = g_start[a.w];
            int s4 = g_start[b.x], s5 = g_start[b.y];
            int s6 = g_start[b.z], s7 = g_start[b.w];
            int base = 8 * i;
            g_perm[s0 + r0.x] = base;
            g_perm[s1 + r0.y] = base + 1;
            g_perm[s2 + r0.z] = base + 2;
            g_perm[s3 + r0.w] = base + 3;
            g_perm[s4 + r1.x] = base + 4;
            g_perm[s5 + r1.y] = base + 5;
            g_perm[s6 + r1.z] = base + 6;
            g_perm[s7 + r1.w] = base + 7;
        }
    }
    for (int i = M8 * 8 + t; i < M; i += stride) {
        int id = load_id(ids, i, is64);
        g_perm[g_start[id] + g_rank[i]] = i;
    }
}

// One warp per node; D == 128 (32 float4 per row, 1 per lane), 2-deep pipeline.
// Also writes iota ids output and re-zeroes g_count for the next execution.
__global__ void gather_kernel(const float4* __restrict__ msgs4,
                              float* __restrict__ out,
                              float* __restrict__ ids_out,
                              int N, int has_ids) {
    int gw   = (blockIdx.x * blockDim.x + threadIdx.x) >> 5;
    int lane = threadIdx.x & 31;
    if (gw >= N) return;

    int cnt   = g_count[gw];
    int start = g_start[gw];
    float4 acc = make_float4(0.f, 0.f, 0.f, 0.f);

    if (cnt > 0) {
        int idx  = g_perm[start];
        int idxn = (cnt > 1) ? g_perm[start + 1] : 0;
        float4 v = __ldg(&msgs4[(size_t)idx * 32 + lane]);
        for (int j = 1; j < cnt; j++) {
            int idxn2 = (j + 1 < cnt) ? g_perm[start + j + 1] : 0;
            float4 v2 = __ldg(&msgs4[(size_t)idxn * 32 + lane]);
            acc.x += v.x; acc.y += v.y; acc.z += v.z; acc.w += v.w;
            v = v2; idxn = idxn2;
        }
        acc.x += v.x; acc.y += v.y; acc.z += v.z; acc.w += v.w;
    }

    float inv = (cnt > 0) ? (1.0f / (float)cnt) : 0.0f;
    acc.x *= inv; acc.y *= inv; acc.z *= inv; acc.w *= inv;
    ((float4*)out)[(size_t)gw * 32 + lane] = acc;

    if (lane == 0) g_count[gw] = 0;                      // zero for next execution
    if (lane == 1 && has_ids) ids_out[gw] = (float)gw;   // iota ids output
}

// ---------- fallback path (generic D / oversized shapes) ----------
__device__ __forceinline__ void red_add_v4(float* addr, float4 v) {
    asm volatile("red.global.add.v4.f32 [%0], {%1, %2, %3, %4};"
                 :: "l"(addr), "f"(v.x), "f"(v.y), "f"(v.z), "f"(v.w) : "memory");
}
__device__ __forceinline__ void red_add_f32(float* addr, float v) {
    asm volatile("red.global.add.f32 [%0], %1;"
                 :: "l"(addr), "f"(v) : "memory");
}

__global__ void fb_init_kernel(float* __restrict__ sums, float* __restrict__ ids_out,
                               int N, int D, int has_ids) {
    long long total = (long long)N * D;
    for (long long i = blockIdx.x * (long long)blockDim.x + threadIdx.x;
         i < total; i += (long long)gridDim.x * blockDim.x)
        sums[i] = 0.f;
    for (long long i = blockIdx.x * (long long)blockDim.x + threadIdx.x;
         i < N; i += (long long)gridDim.x * blockDim.x) {
        if (i < MAX_NODES) g_fcounts[i] = 0.f;
        if (has_ids) ids_out[i] = (float)i;
    }
}

__global__ void fb_scatter_kernel(const void* __restrict__ ids,
                                  const float* __restrict__ msgs,
                                  float* __restrict__ sums, int M, int D) {
    bool is64 = detect_is64_block((const unsigned int*)ids, M);
    int gwarp = (blockIdx.x * blockDim.x + threadIdx.x) >> 5;
    int lane  = threadIdx.x & 31;
    if (gwarp >= M) return;
    int id = load_id(ids, gwarp, is64);
    const float* row = msgs + (size_t)gwarp * D;
    float* dst = sums + (size_t)id * D;
    for (int c = lane * 4; c + 3 < D; c += 128)
        red_add_v4(dst + c, *(const float4*)(row + c));
    for (int c = (D / 4) * 4 + lane; c < D; c += 32)
        red_add_f32(dst + c, row[c]);
    if (lane == 0) red_add_f32(&g_fcounts[id], 1.0f);
}

__global__ void fb_normalize_kernel(float* __restrict__ sums, int N, int D) {
    long long total = (long long)N * D;
    for (long long i = blockIdx.x * (long long)blockDim.x + threadIdx.x;
         i < total; i += (long long)gridDim.x * blockDim.x) {
        int row = (int)(i / D);
        float inv = 1.0f / fmaxf(g_fcounts[row], 1.0f);
        sums[i] *= inv;
    }
}

extern "C" void kernel_launch(void* const* d_in, const int* in_sizes, int n_in,
                              void* d_out, int out_size) {
    const void*  ids  = d_in[0];
    const float* msgs = (const float*)d_in[1];

    int M = in_sizes[0];
    int D = in_sizes[1] / M;   // 128

    int N, has_ids;
    if (out_size % (D + 1) == 0) { N = out_size / (D + 1); has_ids = 1; }
    else                          { N = out_size / D;       has_ids = 0; }

    float* out     = (float*)d_out;
    float* ids_out = out;
    float* sums    = has_ids ? (out + N) : out;

    int nb = (N + SCAN_TILE - 1) / SCAN_TILE;
    bool fast = (D == 128) && (N <= MAX_NODES) && (M <= PERM_CAP) && (nb <= SCAN_THREADS);

    if (fast) {
        {
            int blocks = (M / 4 + 255) / 256; if (blocks > 2048) blocks = 2048;
            if (blocks < 1) blocks = 1;
            rank_kernel<<<blocks, 256>>>(ids, M);
        }
        scan_partial<<<nb, SCAN_THREADS>>>(N);
        scan_final<<<nb, SCAN_THREADS>>>(N, nb);
        {
            int blocks = (M / 8 + 255) / 256; if (blocks > 2048) blocks = 2048;
            if (blocks < 1) blocks = 1;
            place_kernel<<<blocks, 256>>>(ids, M);
        }
        {
            long long threads = (long long)N * 32;
            int blocks = (int)((threads + 255) / 256);
            gather_kernel<<<blocks, 256>>>((const float4*)msgs, sums, ids_out, N, has_ids);
        }
    } else {
        {
            long long total = (long long)N * D;
            int blocks = (int)((total + 255) / 256); if (blocks > 4096) blocks = 4096;
            fb_init_kernel<<<blocks, 256>>>(sums, ids_out, N, D, has_ids);
        }
        {
            long long threads = (long long)M * 32;
            int blocks = (int)((threads + 255) / 256);
            fb_scatter_kernel<<<blocks, 256>>>(ids, msgs, sums, M, D);
        }
        {
            long long total = (long long)N * D;
            int blocks = (int)((total + 255) / 256); if (blocks > 4096) blocks = 4096;
            fb_normalize_kernel<<<blocks, 256>>>(sums, N, D);
        }
    }
}

// round 13
// speedup vs baseline: 1.2536x; 1.0523x over previous
#include <cuda_runtime.h>
#include <cuda_bf16.h>
#include <stdint.h>

// Scatter-mean via counting-sort + gather (no atomics in the hot loop).
// Pipeline (5 launches): rank (inline dtype detect + hist + rank-within-node,
// only atomic pass) -> scan_partial -> scan_final (inline tops) -> place
// (atomic-free, 4-wide) -> gather (2-deep pipeline, L1-bypass streaming row
// loads; writes iota ids, re-zeroes g_count for the next graph replay).
// Fallback to a direct-atomic path for shapes exceeding static scratch.

#define MAX_NODES (1 << 20)
#define PERM_CAP  (1 << 21)
#define SCAN_TILE 1024
#define SCAN_THREADS 512
#define MAX_SCAN_BLOCKS ((MAX_NODES + SCAN_TILE - 1) / SCAN_TILE)

__device__ int g_count[MAX_NODES];       // zero at entry of every execution
__device__ int g_start[MAX_NODES];
__device__ int g_rank[PERM_CAP];
__device__ int g_perm[PERM_CAP];
__device__ int g_bsum[MAX_SCAN_BLOCKS];
__device__ float g_fcounts[MAX_NODES];   // fallback path only

// Streaming 16B load: read-once data, bypass L1 allocation.
__device__ __forceinline__ float4 ldg_stream_v4(const float4* p) {
    float4 v;
    asm volatile("ld.global.nc.L1::no_allocate.v4.f32 {%0, %1, %2, %3}, [%4];"
                 : "=f"(v.x), "=f"(v.y), "=f"(v.z), "=f"(v.w) : "l"(p));
    return v;
}

// Per-block inline dtype detection: examine 256 odd-position 32-bit words from
// this block's own region. int64 ids < 2^32 have all-zero high words; int32
// random ids make some odd word nonzero with overwhelming probability. The
// degenerate all-zero case decodes identically either way.
__device__ __forceinline__ bool detect_is64_block(const unsigned int* words, int M) {
    int t = threadIdx.x & 255;
    int span = M >> 1;                 // number of (even,odd) pairs within M words
    unsigned int w = 0u;
    if (span > 0) {
        int wbase = (int)blockIdx.x * 256;
        if (span > 256) wbase %= (span - 255); else wbase = 0;
        int p = wbase + t;
        if (p < span) w = words[2 * p + 1];
    }
    return __syncthreads_or((int)w) == 0;   // all high words zero -> int64
}

__device__ __forceinline__ int load_id(const void* ids, int i, bool is64) {
    return is64 ? (int)((const long long*)ids)[i] : ((const int*)ids)[i];
}

// Histogram + rank-within-node: the only returning-atomic pass.
// 4 independent atomic chains in flight per thread-iteration.
__global__ void rank_kernel(const void* __restrict__ ids, int M) {
    bool is64 = detect_is64_block((const unsigned int*)ids, M);
    int t = blockIdx.x * blockDim.x + threadIdx.x;
    int stride = gridDim.x * blockDim.x;
    int M4 = M >> 2;
    if (is64) {
        const longlong2* p = (const longlong2*)ids;
        for (int i = t; i < M4; i += stride) {
            longlong2 a = p[2 * i], b = p[2 * i + 1];
            int r0 = atomicAdd(&g_count[(int)a.x], 1);
            int r1 = atomicAdd(&g_count[(int)a.y], 1);
            int r2 = atomicAdd(&g_count[(int)b.x], 1);
            int r3 = atomicAdd(&g_count[(int)b.y], 1);
            ((int4*)g_rank)[i] = make_int4(r0, r1, r2, r3);
        }
    } else {
        const int4* p = (const int4*)ids;
        for (int i = t; i < M4; i += stride) {
            int4 a = p[i];
            int r0 = atomicAdd(&g_count[a.x], 1);
            int r1 = atomicAdd(&g_count[a.y], 1);
            int r2 = atomicAdd(&g_count[a.z], 1);
            int r3 = atomicAdd(&g_count[a.w], 1);
            ((int4*)g_rank)[i] = make_int4(r0, r1, r2, r3);
        }
    }
    for (int i = M4 * 4 + t; i < M; i += stride)
        g_rank[i] = atomicAdd(&g_count[load_id(ids, i, is64)], 1);
}

// ----- 2-stage scan: partial sums -> final rescan with inline tops scan -----
__global__ void scan_partial(int N) {
    __shared__ int wsum[SCAN_THREADS / 32];
    int b = blockIdx.x, tid = threadIdx.x;
    int lane = tid & 31, warp = tid >> 5;
    int base = b * SCAN_TILE + tid * 2;
    int s = 0;
    #pragma unroll
    for (int k = 0; k < 2; k++) {
        int i = base + k;
        if (i < N) s += g_count[i];
    }
    #pragma unroll
    for (int o = 16; o > 0; o >>= 1) s += __shfl_down_sync(0xffffffffu, s, o);
    if (lane == 0) wsum[warp] = s;
    __syncthreads();
    if (warp == 0) {
        int w = (lane < SCAN_THREADS / 32) ? wsum[lane] : 0;
        #pragma unroll
        for (int o = 16; o > 0; o >>= 1) w += __shfl_down_sync(0xffffffffu, w, o);
        if (lane == 0) g_bsum[b] = w;
    }
}

__global__ void scan_final(int N, int nb) {
    __shared__ int wsum[32];
    __shared__ int sboff[1024];
    int b = blockIdx.x, tid = threadIdx.x;
    int lane = tid & 31, warp = tid >> 5;

    // Inline exclusive scan of the nb block sums (nb <= SCAN_THREADS).
    {
        int s = (tid < nb) ? g_bsum[tid] : 0;
        int x = s;
        #pragma unroll
        for (int o = 1; o < 32; o <<= 1) {
            int y = __shfl_up_sync(0xffffffffu, x, o);
            if (lane >= o) x += y;
        }
        if (lane == 31) wsum[warp] = x;
        __syncthreads();
        if (warp == 0) {
            int w = (lane < SCAN_THREADS / 32) ? wsum[lane] : 0;
            #pragma unroll
            for (int o = 1; o < 32; o <<= 1) {
                int y = __shfl_up_sync(0xffffffffu, w, o);
                if (lane >= o) w += y;
            }
            wsum[lane] = w;
        }
        __syncthreads();
        if (tid < nb) sboff[tid] = x - s + (warp > 0 ? wsum[warp - 1] : 0);
        __syncthreads();
    }
    int boff = sboff[b];
    __syncthreads();   // wsum reuse below

    int base = b * SCAN_TILE + tid * 2;
    int v[2]; int s = 0;
    #pragma unroll
    for (int k = 0; k < 2; k++) {
        int i = base + k;
        v[k] = (i < N) ? g_count[i] : 0;
        s += v[k];
    }
    int x = s;
    #pragma unroll
    for (int o = 1; o < 32; o <<= 1) {
        int y = __shfl_up_sync(0xffffffffu, x, o);
        if (lane >= o) x += y;
    }
    if (lane == 31) wsum[warp] = x;
    __syncthreads();
    if (warp == 0) {
        int w = (lane < SCAN_THREADS / 32) ? wsum[lane] : 0;
        #pragma unroll
        for (int o = 1; o < 32; o <<= 1) {
            int y = __shfl_up_sync(0xffffffffu, w, o);
            if (lane >= o) w += y;
        }
        wsum[lane] = w;
    }
    __syncthreads();
    int run = x - s + (warp > 0 ? wsum[warp - 1] : 0) + boff;
    #pragma unroll
    for (int k = 0; k < 2; k++) {
        int i = base + k;
        if (i < N) {
            g_start[i] = run;
            run += v[k];
        }
    }
}

// Atomic-free permutation: perm[start[id] + rank[i]] = i. 4-wide.
__global__ void place_kernel(const void* __restrict__ ids, int M) {
    bool is64 = detect_is64_block((const unsigned int*)ids, M);
    int t = blockIdx.x * blockDim.x + threadIdx.x;
    int stride = gridDim.x * blockDim.x;
    int M4 = M >> 2;
    if (is64) {
        const longlong2* p = (const longlong2*)ids;
        for (int i = t; i < M4; i += stride) {
            longlong2 a = p[2 * i], b = p[2 * i + 1];
            int4 r = ((const int4*)g_rank)[i];
            int base = 4 * i;
            g_perm[g_start[(int)a.x] + r.x] = base;
            g_perm[g_start[(int)a.y] + r.y] = base + 1;
            g_perm[g_start[(int)b.x] + r.z] = base + 2;
            g_perm[g_start[(int)b.y] + r.w] = base + 3;
        }
    } else {
        const int4* p = (const int4*)ids;
        for (int i = t; i < M4; i += stride) {
            int4 a = p[i];
            int4 r = ((const int4*)g_rank)[i];
            int base = 4 * i;
            g_perm[g_start[a.x] + r.x] = base;
            g_perm[g_start[a.y] + r.y] = base + 1;
            g_perm[g_start[a.z] + r.z] = base + 2;
            g_perm[g_start[a.w] + r.w] = base + 3;
        }
    }
    for (int i = M4 * 4 + t; i < M; i += stride) {
        int id = load_id(ids, i, is64);
        g_perm[g_start[id] + g_rank[i]] = i;
    }
}

// One warp per node; D == 128 (32 float4 per row, 1 per lane), 2-deep pipeline.
// Row loads bypass L1 (read-once streaming). Also writes iota ids output and
// re-zeroes g_count for the next execution.
__global__ void gather_kernel(const float4* __restrict__ msgs4,
                              float* __restrict__ out,
                              float* __restrict__ ids_out,
                              int N, int has_ids) {
    int gw   = (blockIdx.x * blockDim.x + threadIdx.x) >> 5;
    int lane = threadIdx.x & 31;
    if (gw >= N) return;

    int cnt   = g_count[gw];
    int start = g_start[gw];
    float4 acc = make_float4(0.f, 0.f, 0.f, 0.f);

    if (cnt > 0) {
        int idx  = g_perm[start];
        int idxn = (cnt > 1) ? g_perm[start + 1] : 0;
        float4 v = ldg_stream_v4(&msgs4[(size_t)idx * 32 + lane]);
        for (int j = 1; j < cnt; j++) {
            int idxn2 = (j + 1 < cnt) ? g_perm[start + j + 1] : 0;
            float4 v2 = ldg_stream_v4(&msgs4[(size_t)idxn * 32 + lane]);
            acc.x += v.x; acc.y += v.y; acc.z += v.z; acc.w += v.w;
            v = v2; idxn = idxn2;
        }
        acc.x += v.x; acc.y += v.y; acc.z += v.z; acc.w += v.w;
    }

    float inv = (cnt > 0) ? (1.0f / (float)cnt) : 0.0f;
    acc.x *= inv; acc.y *= inv; acc.z *= inv; acc.w *= inv;
    ((float4*)out)[(size_t)gw * 32 + lane] = acc;

    if (lane == 0) g_count[gw] = 0;                      // zero for next execution
    if (lane == 1 && has_ids) ids_out[gw] = (float)gw;   // iota ids output
}

// ---------- fallback path (generic D / oversized shapes) ----------
__device__ __forceinline__ void red_add_v4(float* addr, float4 v) {
    asm volatile("red.global.add.v4.f32 [%0], {%1, %2, %3, %4};"
                 :: "l"(addr), "f"(v.x), "f"(v.y), "f"(v.z), "f"(v.w) : "memory");
}
__device__ __forceinline__ void red_add_f32(float* addr, float v) {
    asm volatile("red.global.add.f32 [%0], %1;"
                 :: "l"(addr), "f"(v) : "memory");
}

__global__ void fb_init_kernel(float* __restrict__ sums, float* __restrict__ ids_out,
                               int N, int D, int has_ids) {
    long long total = (long long)N * D;
    for (long long i = blockIdx.x * (long long)blockDim.x + threadIdx.x;
         i < total; i += (long long)gridDim.x * blockDim.x)
        sums[i] = 0.f;
    for (long long i = blockIdx.x * (long long)blockDim.x + threadIdx.x;
         i < N; i += (long long)gridDim.x * blockDim.x) {
        if (i < MAX_NODES) g_fcounts[i] = 0.f;
        if (has_ids) ids_out[i] = (float)i;
    }
}

__global__ void fb_scatter_kernel(const void* __restrict__ ids,
                                  const float* __restrict__ msgs,
                                  float* __restrict__ sums, int M, int D) {
    bool is64 = detect_is64_block((const unsigned int*)ids, M);
    int gwarp = (blockIdx.x * blockDim.x + threadIdx.x) >> 5;
    int lane  = threadIdx.x & 31;
    if (gwarp >= M) return;
    int id = load_id(ids, gwarp, is64);
    const float* row = msgs + (size_t)gwarp * D;
    float* dst = sums + (size_t)id * D;
    for (int c = lane * 4; c + 3 < D; c += 128)
        red_add_v4(dst + c, *(const float4*)(row + c));
    for (int c = (D / 4) * 4 + lane; c < D; c += 32)
        red_add_f32(dst + c, row[c]);
    if (lane == 0) red_add_f32(&g_fcounts[id], 1.0f);
}

__global__ void fb_normalize_kernel(float* __restrict__ sums, int N, int D) {
    long long total = (long long)N * D;
    for (long long i = blockIdx.x * (long long)blockDim.x + threadIdx.x;
         i < total; i += (long long)gridDim.x * blockDim.x) {
        int row = (int)(i / D);
        float inv = 1.0f / fmaxf(g_fcounts[row], 1.0f);
        sums[i] *= inv;
    }
}

extern "C" void kernel_launch(void* const* d_in, const int* in_sizes, int n_in,
                              void* d_out, int out_size) {
    const void*  ids  = d_in[0];
    const float* msgs = (const float*)d_in[1];

    int M = in_sizes[0];
    int D = in_sizes[1] / M;   // 128

    int N, has_ids;
    if (out_size % (D + 1) == 0) { N = out_size / (D + 1); has_ids = 1; }
    else                          { N = out_size / D;       has_ids = 0; }

    float* out     = (float*)d_out;
    float* ids_out = out;
    float* sums    = has_ids ? (out + N) : out;

    int nb = (N + SCAN_TILE - 1) / SCAN_TILE;
    bool fast = (D == 128) && (N <= MAX_NODES) && (M <= PERM_CAP) && (nb <= SCAN_THREADS);

    if (fast) {
        {
            int blocks = (M / 4 + 255) / 256; if (blocks > 2048) blocks = 2048;
            if (blocks < 1) blocks = 1;
            rank_kernel<<<blocks, 256>>>(ids, M);
        }
        scan_partial<<<nb, SCAN_THREADS>>>(N);
        scan_final<<<nb, SCAN_THREADS>>>(N, nb);
        {
            int blocks = (M / 4 + 255) / 256; if (blocks > 2048) blocks = 2048;
            if (blocks < 1) blocks = 1;
            place_kernel<<<blocks, 256>>>(ids, M);
        }
        {
            long long threads = (long long)N * 32;
            int blocks = (int)((threads + 255) / 256);
            gather_kernel<<<blocks, 256>>>((const float4*)msgs, sums, ids_out, N, has_ids);
        }
    } else {
        {
            long long total = (long long)N * D;
            int blocks = (int)((total + 255) / 256); if (blocks > 4096) blocks = 4096;
            fb_init_kernel<<<blocks, 256>>>(sums, ids_out, N, D, has_ids);
        }
        {
            long long threads = (long long)M * 32;
            int blocks = (int)((threads + 255) / 256);
            fb_scatter_kernel<<<blocks, 256>>>(ids, msgs, sums, M, D);
        }
        {
            long long total = (long long)N * D;
            int blocks = (int)((total + 255) / 256); if (blocks > 4096) blocks = 4096;
            fb_normalize_kernel<<<blocks, 256>>>(sums, N, D);
        }
    }
}